// round 6
// baseline (speedup 1.0000x reference)
#include <cuda_runtime.h>

// LSTM1: B=4096, T=2048, I=6, H=2. Two threads per sequence (parity p owns
// hidden lane p). Software-pipelined: the x-projection xacc = b + W_x*x for
// all 4 steps of the NEXT chunk is computed while the current chunk's
// recurrence chain (h-FMAs -> tanh -> c -> tanh -> shfl) runs, so the chain
// never waits on the x accumulation. Sigmoid 0.5 pre-folded into i/f/o.

#define B_DIM 4096
#define T_DIM 2048
#define I_DIM 6

__device__ __forceinline__ float tanh_ap(float x) {
    float y; asm("tanh.approx.f32 %0, %1;" : "=f"(y) : "f"(x)); return y;
}

// Recurrence-only step: gates = xacc[r] + h_own*whO[r] + h_peer*whP[r].
// Peer-term FMA is outermost (shortest path from the shfl result).
__device__ __forceinline__ void lstm_step_rec(
    const float (&xs)[4],
    const float (&whO)[4], const float (&whP)[4],
    float& c, float& h_own, float& h_peer)
{
    const float g0 = fmaf(h_peer, whP[0], fmaf(h_own, whO[0], xs[0]));
    const float g1 = fmaf(h_peer, whP[1], fmaf(h_own, whO[1], xs[1]));
    const float g2 = fmaf(h_peer, whP[2], fmaf(h_own, whO[2], xs[2]));
    const float g3 = fmaf(h_peer, whP[3], fmaf(h_own, whO[3], xs[3]));

    const float ig = fmaf(tanh_ap(g0), 0.5f, 0.5f);
    const float fg = fmaf(tanh_ap(g1), 0.5f, 0.5f);
    const float gg = tanh_ap(g2);
    const float og = fmaf(tanh_ap(g3), 0.5f, 0.5f);

    c = fmaf(fg, c, ig * gg);
    h_own = og * tanh_ap(c);
    h_peer = __shfl_xor_sync(0xFFFFFFFFu, h_own, 1);
}

// Fill xacc[step][row] for one 4-step chunk from 6 float4 (24 x values).
__device__ __forceinline__ void fill_xacc(
    float (&xa)[4][4],
    const float4 f0, const float4 f1, const float4 f2,
    const float4 f3, const float4 f4, const float4 f5,
    const float (&w)[4][6], const float (&bs)[4])
{
    const float xs[4][6] = {
        {f0.x, f0.y, f0.z, f0.w, f1.x, f1.y},
        {f1.z, f1.w, f2.x, f2.y, f2.z, f2.w},
        {f3.x, f3.y, f3.z, f3.w, f4.x, f4.y},
        {f4.z, f4.w, f5.x, f5.y, f5.z, f5.w}};
#pragma unroll
    for (int s = 0; s < 4; s++) {
#pragma unroll
        for (int r = 0; r < 4; r++) {
            // Two partial chains joined at the end: row latency ~16 cyc, all
            // independent of the recurrence chain.
            float a = fmaf(xs[s][0], w[r][0], bs[r]);
            a = fmaf(xs[s][1], w[r][1], a);
            a = fmaf(xs[s][2], w[r][2], a);
            float bacc = xs[s][3] * w[r][3];
            bacc = fmaf(xs[s][4], w[r][4], bacc);
            bacc = fmaf(xs[s][5], w[r][5], bacc);
            xa[s][r] = a + bacc;
        }
    }
}

__global__ void __launch_bounds__(64, 1) lstm_fused_kernel(
    const float* __restrict__ x,
    const float* __restrict__ w_ih, const float* __restrict__ w_hh,
    const float* __restrict__ b_ih, const float* __restrict__ b_hh,
    const float* __restrict__ fc1_w, const float* __restrict__ fc1_b,
    const float* __restrict__ fc_w, const float* __restrict__ fc_b,
    float* __restrict__ out)
{
    const int tid = blockIdx.x * 64 + threadIdx.x;   // 8192 threads
    const int seq = tid >> 1;
    const int p = tid & 1;

    // Gate rows for lane p (PyTorch i,f,g,o order, H=2): gr = 2r + p.
    float w[4][6], whO[4], whP[4], bs[4];
#pragma unroll
    for (int r = 0; r < 4; r++) {
        const int gr = 2 * r + p;
        const float s = (r == 2) ? 1.0f : 0.5f;      // g-gate unscaled
#pragma unroll
        for (int i = 0; i < 6; i++) w[r][i] = s * w_ih[gr * 6 + i];
        whO[r] = s * w_hh[gr * 2 + p];
        whP[r] = s * w_hh[gr * 2 + (1 - p)];
        bs[r] = s * (b_ih[gr] + b_hh[gr]);
    }

    const float4* xb4 = (const float4*)(x + (size_t)seq * (T_DIM * I_DIM));
    float c = 0.f, h_own = 0.f, h_peer = 0.f;

    const int NCH = T_DIM / 4;  // 512 chunks of 4 steps

    // Prologue: xacc for chunk 0.
    float xa[2][4][4];
    {
        const float4 f0 = xb4[0], f1 = xb4[1], f2 = xb4[2],
                     f3 = xb4[3], f4 = xb4[4], f5 = xb4[5];
        fill_xacc(xa[0], f0, f1, f2, f3, f4, f5, w, bs);
    }

#pragma unroll 2
    for (int k = 0; k < NCH; k++) {
        const int cur = k & 1, nxt = cur ^ 1;
        const int kn = (k + 1 < NCH) ? (k + 1) : k;
        const float4* nb = xb4 + 6 * kn;
        const float4 f0 = nb[0], f1 = nb[1], f2 = nb[2],
                     f3 = nb[3], f4 = nb[4], f5 = nb[5];
        if (k + 16 < NCH)
            asm volatile("prefetch.global.L2 [%0];" :: "l"(xb4 + 6 * (k + 16)));

        // Next chunk's x-projection: fully independent of the chain below;
        // the scheduler interleaves these FMAs into the chain's stall slots.
        fill_xacc(xa[nxt], f0, f1, f2, f3, f4, f5, w, bs);

        lstm_step_rec(xa[cur][0], whO, whP, c, h_own, h_peer);
        lstm_step_rec(xa[cur][1], whO, whP, c, h_own, h_peer);
        lstm_step_rec(xa[cur][2], whO, whP, c, h_own, h_peer);
        lstm_step_rec(xa[cur][3], whO, whP, c, h_own, h_peer);
    }

    // Head on even threads: h0 = h_own, h1 = h_peer.
    if (p == 0) {
        const float r0 = fmaxf(h_own, 0.f), r1 = fmaxf(h_peer, 0.f);
        float acc = fc_b[0];
#pragma unroll 8
        for (int j = 0; j < 128; j++) {
            const float2 wv = ((const float2*)fc1_w)[j];
            float v = fmaf(wv.x, r0, fmaf(wv.y, r1, fc1_b[j]));
            v = fmaxf(v, 0.f);
            acc = fmaf(v, fc_w[j], acc);
        }
        out[seq] = acc;
    }
}

extern "C" void kernel_launch(void* const* d_in, const int* in_sizes, int n_in,
                              void* d_out, int out_size) {
    (void)in_sizes; (void)n_in; (void)out_size;
    lstm_fused_kernel<<<(2 * B_DIM) / 64, 64>>>(
        (const float*)d_in[0],  // x
        (const float*)d_in[1],  // w_ih
        (const float*)d_in[2],  // w_hh
        (const float*)d_in[3],  // b_ih
        (const float*)d_in[4],  // b_hh
        (const float*)d_in[5],  // fc1_w
        (const float*)d_in[6],  // fc1_b
        (const float*)d_in[7],  // fc_w
        (const float*)d_in[8],  // fc_b
        (float*)d_out);
}